// round 2
// baseline (speedup 1.0000x reference)
#include <cuda_runtime.h>
#include <math.h>
#include <stdint.h>

#define DIM 128
#define F 64
#define NG 50
#define NMAX 100352

// Distance -> (W * C) lookup table: 8192 intervals over [0, 13], rows 0..8192
#define TAB_INTERVALS 8192
#define TAB_ROWS (TAB_INTERVALS + 1)
#define TAB_MAXD 13.0f

static __device__ __align__(16) float g_tab[(size_t)TAB_ROWS * F + 64];
static __device__ __align__(16) float g_h1[(size_t)NMAX * F];
static __device__ __align__(16) float g_agg[(size_t)NMAX * F];

__device__ __forceinline__ float sspf(float v) {
    // softplus(v) - log(2), numerically stable
    return fmaxf(v, 0.0f) + log1pf(expf(-fabsf(v))) - 0.69314718055994531f;
}

// ---------------------------------------------------------------------------
// Kernel 1: build the dist -> W*C table.  One block (64 threads) per row.
// ---------------------------------------------------------------------------
__global__ void table_kernel(const float* __restrict__ w1, const float* __restrict__ b1,
                             const float* __restrict__ w2, const float* __restrict__ b2) {
    __shared__ float hid[F];
    int e = blockIdx.x;
    int f = threadIdx.x;  // 0..63
    float dist = (float)e * (TAB_MAXD / (float)TAB_INTERVALS);

    const float dOff  = 10.0f / 49.0f;                 // linspace(0,10,50) spacing
    const float coeff = -0.5f / (dOff * dOff);

    float pre = b1[f];
#pragma unroll 1
    for (int i = 0; i < NG; i++) {
        float d  = dist - (float)i * dOff;
        float ea = expf(coeff * d * d);
        pre = fmaf(ea, w1[i * F + f], pre);
    }
    hid[f] = sspf(pre);
    __syncthreads();

    float o = b2[f];
#pragma unroll 1
    for (int i = 0; i < F; i++) o = fmaf(hid[i], w2[i * F + f], o);

    float C = 0.5f * (cosf(dist * (float)(M_PI / 10.0)) + 1.0f);
    g_tab[(size_t)e * F + f] = o * C;
}

// ---------------------------------------------------------------------------
// Kernel 2: zero the aggregation buffer.
// ---------------------------------------------------------------------------
__global__ void zero_agg_kernel(int n4) {
    int i = blockIdx.x * blockDim.x + threadIdx.x;
    if (i < n4) reinterpret_cast<float4*>(g_agg)[i] = make_float4(0.f, 0.f, 0.f, 0.f);
}

// ---------------------------------------------------------------------------
// Kernel 3: h1 = x @ conv_lin1_w   [N,128] @ [128,64] -> [N,64]
// 128-row x 64-col tiles, 256 threads, k-chunks of 32, register tile 8x4.
// ---------------------------------------------------------------------------
__global__ void gemm1_kernel(const float* __restrict__ x, const float* __restrict__ w, int N) {
    __shared__ float xs[128 * 33];
    __shared__ float ws[32 * 64];
    int tid = threadIdx.x;
    int ct = tid & 15;   // 16 col-threads * 4 cols = 64
    int rt = tid >> 4;   // 16 row-threads * 8 rows = 128
    float acc[8][4];
#pragma unroll
    for (int i = 0; i < 8; i++)
#pragma unroll
        for (int j = 0; j < 4; j++) acc[i][j] = 0.f;

    int row0 = blockIdx.x * 128;

    for (int kc = 0; kc < DIM; kc += 32) {
        // load x chunk [128][32]
        {
            int r  = tid >> 3;        // 0..31
            int c4 = (tid & 7) * 4;   // 0..28
#pragma unroll
            for (int rr = 0; rr < 4; rr++) {
                int row = r + rr * 32;
                int gr = row0 + row;
                float4 v = make_float4(0.f, 0.f, 0.f, 0.f);
                if (gr < N)
                    v = *reinterpret_cast<const float4*>(x + (size_t)gr * DIM + kc + c4);
                float* p = xs + row * 33 + c4;
                p[0] = v.x; p[1] = v.y; p[2] = v.z; p[3] = v.w;
            }
        }
        // load w chunk [32][64]
        for (int i = tid; i < 512; i += 256)
            reinterpret_cast<float4*>(ws)[i] =
                reinterpret_cast<const float4*>(w + (size_t)kc * F)[i];
        __syncthreads();

#pragma unroll 4
        for (int k = 0; k < 32; k++) {
            float4 b = reinterpret_cast<const float4*>(ws + k * F)[ct];
#pragma unroll
            for (int i = 0; i < 8; i++) {
                float a = xs[(rt * 8 + i) * 33 + k];
                acc[i][0] = fmaf(a, b.x, acc[i][0]);
                acc[i][1] = fmaf(a, b.y, acc[i][1]);
                acc[i][2] = fmaf(a, b.z, acc[i][2]);
                acc[i][3] = fmaf(a, b.w, acc[i][3]);
            }
        }
        __syncthreads();
    }

#pragma unroll
    for (int i = 0; i < 8; i++) {
        int gr = row0 + rt * 8 + i;
        if (gr < N) {
            float4 v = make_float4(acc[i][0], acc[i][1], acc[i][2], acc[i][3]);
            reinterpret_cast<float4*>(g_h1)[(size_t)gr * 16 + ct] = v;
        }
    }
}

// ---------------------------------------------------------------------------
// Kernel 4: edge scatter.  Half-warp (16 lanes) per edge; lane handles 4 cols.
// msg = h1[src] * lerp(tab, dist)  ->  red.v4 into agg[dst]
// edge_index is INT32 (JAX default x64-disabled downcasts jnp.int64).
// ---------------------------------------------------------------------------
__global__ void edge_kernel(const int* __restrict__ ei,
                            const float* __restrict__ pos, int E) {
    const float INV_STEP = (float)TAB_INTERVALS / TAB_MAXD;
    int lane = threadIdx.x & 31;
    int sub  = lane & 15;
    long long widx = (long long)blockIdx.x * (blockDim.x >> 5) + (threadIdx.x >> 5);
    long long e = widx * 2 + (lane >> 4);
    bool valid = (e < E);

    int src = 0, dst = 0;
    float t = 0.f;
    if (sub == 0 && valid) {
        src = ei[e];
        dst = ei[E + e];
        float ax = pos[(size_t)src * 3 + 0], ay = pos[(size_t)src * 3 + 1], az = pos[(size_t)src * 3 + 2];
        float bx = pos[(size_t)dst * 3 + 0], by = pos[(size_t)dst * 3 + 1], bz = pos[(size_t)dst * 3 + 2];
        float dx = bx - ax, dy = by - ay, dz = bz - az;
        float dist = sqrtf(fmaf(dx, dx, fmaf(dy, dy, dz * dz)));
        t = fminf(dist, TAB_MAXD) * INV_STEP;
    }
    src = __shfl_sync(0xffffffffu, src, 0, 16);
    dst = __shfl_sync(0xffffffffu, dst, 0, 16);
    t   = __shfl_sync(0xffffffffu, t,   0, 16);
    if (!valid) return;

    int i0 = (int)t;
    i0 = min(i0, TAB_INTERVALS - 1);
    float frac = t - (float)i0;

    const float4* tr = reinterpret_cast<const float4*>(g_tab) + (size_t)i0 * 16 + sub;
    float4 w0 = tr[0];
    float4 w1 = tr[16];
    float4 w;
    w.x = fmaf(frac, w1.x - w0.x, w0.x);
    w.y = fmaf(frac, w1.y - w0.y, w0.y);
    w.z = fmaf(frac, w1.z - w0.z, w0.z);
    w.w = fmaf(frac, w1.w - w0.w, w0.w);

    float4 h = reinterpret_cast<const float4*>(g_h1)[(size_t)src * 16 + sub];
    float mx = h.x * w.x, my = h.y * w.y, mz = h.z * w.z, mw = h.w * w.w;

    float* ap = g_agg + (size_t)dst * F + sub * 4;
    unsigned long long gap = __cvta_generic_to_global(ap);
    asm volatile("red.global.add.v4.f32 [%0], {%1,%2,%3,%4};"
                 :: "l"(gap), "f"(mx), "f"(my), "f"(mz), "f"(mw) : "memory");
}

// ---------------------------------------------------------------------------
// Kernel 5: fused node tail.
//   h2 = ssp(agg @ w2c + b2c)      [N,64] -> [N,128]
//   h3 = h2 @ int_w + int_b        [N,128]
//   out = x + relu(h3 @ lin1 + b)  [N,128]
// All three weight matrices (160KB) resident in smem; persistent blocks.
// ---------------------------------------------------------------------------
#define TAIL_SMEM_FLOATS (8192 + 16384 + 16384 + 64*130 + 64*130 + 3*128)
#define TAIL_SMEM_BYTES  (TAIL_SMEM_FLOATS * 4)

__global__ void tail_kernel(const float* __restrict__ x,
                            const float* __restrict__ wAg, const float* __restrict__ bAg,
                            const float* __restrict__ wBg, const float* __restrict__ bBg,
                            const float* __restrict__ wCg, const float* __restrict__ bCg,
                            float* __restrict__ out, int N) {
    extern __shared__ float sm[];
    float* wA   = sm;                 // [64][128]
    float* wB   = sm + 8192;          // [128][128]
    float* wC   = sm + 24576;         // [128][128]
    float* buf0 = sm + 40960;         // [64][130]
    float* buf1 = sm + 49280;         // [64][130]
    float* bias = sm + 57600;         // [3][128]

    int tid = threadIdx.x;
    for (int i = tid; i < 2048; i += 256)
        reinterpret_cast<float4*>(wA)[i] = reinterpret_cast<const float4*>(wAg)[i];
    for (int i = tid; i < 4096; i += 256)
        reinterpret_cast<float4*>(wB)[i] = reinterpret_cast<const float4*>(wBg)[i];
    for (int i = tid; i < 4096; i += 256)
        reinterpret_cast<float4*>(wC)[i] = reinterpret_cast<const float4*>(wCg)[i];
    if (tid < 128) {
        bias[tid]       = bAg[tid];
        bias[128 + tid] = bBg[tid];
        bias[256 + tid] = bCg[tid];
    }
    __syncthreads();

    int ct = tid & 31;   // 32 col-threads * 4 cols = 128
    int rt = tid >> 5;   // 8 row-threads * 8 rows = 64
    int ntiles = (N + 63) / 64;

    for (int tile = blockIdx.x; tile < ntiles; tile += gridDim.x) {
        int row0 = tile * 64;

        // load agg tile [64][64] into buf0
        for (int i = tid; i < 64 * 16; i += 256) {
            int r = i >> 4, c = i & 15;
            int gr = row0 + r;
            float4 v = make_float4(0.f, 0.f, 0.f, 0.f);
            if (gr < N) v = reinterpret_cast<const float4*>(g_agg)[(size_t)gr * 16 + c];
            float* p = buf0 + r * 130 + c * 4;
            p[0] = v.x; p[1] = v.y; p[2] = v.z; p[3] = v.w;
        }
        __syncthreads();

        float acc[8][4];

        // Stage A: agg @ wA   (k = 64)
#pragma unroll
        for (int i = 0; i < 8; i++)
#pragma unroll
            for (int j = 0; j < 4; j++) acc[i][j] = 0.f;
#pragma unroll 4
        for (int k = 0; k < 64; k++) {
            float4 b = reinterpret_cast<const float4*>(wA + k * 128)[ct];
#pragma unroll
            for (int i = 0; i < 8; i++) {
                float a = buf0[(rt * 8 + i) * 130 + k];
                acc[i][0] = fmaf(a, b.x, acc[i][0]);
                acc[i][1] = fmaf(a, b.y, acc[i][1]);
                acc[i][2] = fmaf(a, b.z, acc[i][2]);
                acc[i][3] = fmaf(a, b.w, acc[i][3]);
            }
        }
#pragma unroll
        for (int i = 0; i < 8; i++) {
            float* p = buf1 + (rt * 8 + i) * 130 + ct * 4;
            p[0] = sspf(acc[i][0] + bias[ct * 4 + 0]);
            p[1] = sspf(acc[i][1] + bias[ct * 4 + 1]);
            p[2] = sspf(acc[i][2] + bias[ct * 4 + 2]);
            p[3] = sspf(acc[i][3] + bias[ct * 4 + 3]);
        }
        __syncthreads();

        // Stage B: h2 @ wB   (k = 128) -> buf0
#pragma unroll
        for (int i = 0; i < 8; i++)
#pragma unroll
            for (int j = 0; j < 4; j++) acc[i][j] = 0.f;
#pragma unroll 4
        for (int k = 0; k < 128; k++) {
            float4 b = reinterpret_cast<const float4*>(wB + k * 128)[ct];
#pragma unroll
            for (int i = 0; i < 8; i++) {
                float a = buf1[(rt * 8 + i) * 130 + k];
                acc[i][0] = fmaf(a, b.x, acc[i][0]);
                acc[i][1] = fmaf(a, b.y, acc[i][1]);
                acc[i][2] = fmaf(a, b.z, acc[i][2]);
                acc[i][3] = fmaf(a, b.w, acc[i][3]);
            }
        }
        __syncthreads();   // buf1 reads done before buf0 overwrite below
#pragma unroll
        for (int i = 0; i < 8; i++) {
            float* p = buf0 + (rt * 8 + i) * 130 + ct * 4;
            p[0] = acc[i][0] + bias[128 + ct * 4 + 0];
            p[1] = acc[i][1] + bias[128 + ct * 4 + 1];
            p[2] = acc[i][2] + bias[128 + ct * 4 + 2];
            p[3] = acc[i][3] + bias[128 + ct * 4 + 3];
        }
        __syncthreads();

        // Stage C: h3 @ wC, relu, + x, store
#pragma unroll
        for (int i = 0; i < 8; i++)
#pragma unroll
            for (int j = 0; j < 4; j++) acc[i][j] = 0.f;
#pragma unroll 4
        for (int k = 0; k < 128; k++) {
            float4 b = reinterpret_cast<const float4*>(wC + k * 128)[ct];
#pragma unroll
            for (int i = 0; i < 8; i++) {
                float a = buf0[(rt * 8 + i) * 130 + k];
                acc[i][0] = fmaf(a, b.x, acc[i][0]);
                acc[i][1] = fmaf(a, b.y, acc[i][1]);
                acc[i][2] = fmaf(a, b.z, acc[i][2]);
                acc[i][3] = fmaf(a, b.w, acc[i][3]);
            }
        }
#pragma unroll
        for (int i = 0; i < 8; i++) {
            int gr = row0 + rt * 8 + i;
            if (gr < N) {
                float4 xv = reinterpret_cast<const float4*>(x)[(size_t)gr * 32 + ct];
                float4 o;
                o.x = xv.x + fmaxf(acc[i][0] + bias[256 + ct * 4 + 0], 0.f);
                o.y = xv.y + fmaxf(acc[i][1] + bias[256 + ct * 4 + 1], 0.f);
                o.z = xv.z + fmaxf(acc[i][2] + bias[256 + ct * 4 + 2], 0.f);
                o.w = xv.w + fmaxf(acc[i][3] + bias[256 + ct * 4 + 3], 0.f);
                reinterpret_cast<float4*>(out)[(size_t)gr * 32 + ct] = o;
            }
        }
        __syncthreads();   // before next tile overwrites buf0
    }
}

// ---------------------------------------------------------------------------
extern "C" void kernel_launch(void* const* d_in, const int* in_sizes, int n_in,
                              void* d_out, int out_size) {
    const float* x      = (const float*)d_in[0];
    const float* pos    = (const float*)d_in[1];
    const int*   ei     = (const int*)d_in[2];          // int32 (JAX x64 disabled)
    const float* mlp_w1 = (const float*)d_in[3];
    const float* mlp_b1 = (const float*)d_in[4];
    const float* mlp_w2 = (const float*)d_in[5];
    const float* mlp_b2 = (const float*)d_in[6];
    const float* clin1w = (const float*)d_in[7];
    const float* clin2w = (const float*)d_in[8];
    const float* clin2b = (const float*)d_in[9];
    const float* intw   = (const float*)d_in[10];
    const float* intb   = (const float*)d_in[11];
    const float* l1w    = (const float*)d_in[12];
    const float* l1b    = (const float*)d_in[13];
    float* out = (float*)d_out;

    int N = in_sizes[0] / DIM;
    int E = in_sizes[2] / 2;

    cudaFuncSetAttribute(tail_kernel, cudaFuncAttributeMaxDynamicSharedMemorySize,
                         TAIL_SMEM_BYTES);

    table_kernel<<<TAB_ROWS, 64>>>(mlp_w1, mlp_b1, mlp_w2, mlp_b2);

    int n4 = N * 16;
    zero_agg_kernel<<<(n4 + 255) / 256, 256>>>(n4);

    gemm1_kernel<<<(N + 127) / 128, 256>>>(x, clin1w, N);

    long long eblocks = ((long long)E + 15) / 16;
    edge_kernel<<<(unsigned)eblocks, 256>>>(ei, pos, E);

    tail_kernel<<<148, 256, TAIL_SMEM_BYTES>>>(x, clin2w, clin2b, intw, intb,
                                               l1w, l1b, out, N);
}